// round 4
// baseline (speedup 1.0000x reference)
#include <cuda_runtime.h>
#include <cuda_bf16.h>

#define NC 4
#define D  256

// Scratch: per-class column sums + per-class row counts.
__device__ float        g_sum[NC * D];
__device__ unsigned int g_cnt[NC];

__global__ void zero_kernel() {
    int t = threadIdx.x;
    if (t < NC * D) g_sum[t] = 0.0f;
    if (t < NC)     g_cnt[t] = 0u;
}

// 256 threads/CTA. Each 64-thread group handles one row per iteration:
// row = 64 float4 (256 floats), lane = float4 index within the row.
__global__ __launch_bounds__(256) void accum_kernel(
    const float4* __restrict__ feat,   // [nrows * 64] float4
    const int*    __restrict__ labels, // [nrows] int32
    int nrows)
{
    const int tid  = threadIdx.x;
    const int grp  = tid >> 6;   // 0..3 : which of the 4 rows this CTA covers per step
    const int lane = tid & 63;   // 0..63: float4 column index within the row

    float4 a0 = make_float4(0.f, 0.f, 0.f, 0.f);
    float4 a1 = a0, a2 = a0, a3 = a0;
    int c0 = 0, c1 = 0, c2 = 0, c3 = 0;

    const int rowStride = gridDim.x * 4;

    for (int row = blockIdx.x * 4 + grp; row < nrows; row += rowStride) {
        const int lbl = labels[row];                  // broadcast within the 64-group
        const float4 v = feat[(size_t)row * 64 + lane];

        const float m0 = (lbl == 0) ? 1.f : 0.f;
        const float m1 = (lbl == 1) ? 1.f : 0.f;
        const float m2 = (lbl == 2) ? 1.f : 0.f;
        const float m3 = (lbl == 3) ? 1.f : 0.f;

        a0.x = fmaf(v.x, m0, a0.x); a0.y = fmaf(v.y, m0, a0.y);
        a0.z = fmaf(v.z, m0, a0.z); a0.w = fmaf(v.w, m0, a0.w);
        a1.x = fmaf(v.x, m1, a1.x); a1.y = fmaf(v.y, m1, a1.y);
        a1.z = fmaf(v.z, m1, a1.z); a1.w = fmaf(v.w, m1, a1.w);
        a2.x = fmaf(v.x, m2, a2.x); a2.y = fmaf(v.y, m2, a2.y);
        a2.z = fmaf(v.z, m2, a2.z); a2.w = fmaf(v.w, m2, a2.w);
        a3.x = fmaf(v.x, m3, a3.x); a3.y = fmaf(v.y, m3, a3.y);
        a3.z = fmaf(v.z, m3, a3.z); a3.w = fmaf(v.w, m3, a3.w);

        if (lane == 0) {
            c0 += (lbl == 0); c1 += (lbl == 1);
            c2 += (lbl == 2); c3 += (lbl == 3);
        }
    }

    // Block reduction: smem[class][grp][col] (4*4*256*4B = 16 KB)
    __shared__ float s[NC][4][D];
    __shared__ unsigned int sc[NC][4];

    const int col = lane * 4;
    s[0][grp][col+0] = a0.x; s[0][grp][col+1] = a0.y; s[0][grp][col+2] = a0.z; s[0][grp][col+3] = a0.w;
    s[1][grp][col+0] = a1.x; s[1][grp][col+1] = a1.y; s[1][grp][col+2] = a1.z; s[1][grp][col+3] = a1.w;
    s[2][grp][col+0] = a2.x; s[2][grp][col+1] = a2.y; s[2][grp][col+2] = a2.z; s[2][grp][col+3] = a2.w;
    s[3][grp][col+0] = a3.x; s[3][grp][col+1] = a3.y; s[3][grp][col+2] = a3.z; s[3][grp][col+3] = a3.w;

    if (lane == 0) {
        sc[0][grp] = (unsigned)c0; sc[1][grp] = (unsigned)c1;
        sc[2][grp] = (unsigned)c2; sc[3][grp] = (unsigned)c3;
    }
    __syncthreads();

    // 256 threads: thread -> (class = tid>>6, float4-chunk = tid&63)
    {
        const int c = tid >> 6;
        const int l = tid & 63;
        const int b = l * 4;
        #pragma unroll
        for (int j = 0; j < 4; j++) {
            float v = s[c][0][b + j] + s[c][1][b + j] + s[c][2][b + j] + s[c][3][b + j];
            atomicAdd(&g_sum[c * D + b + j], v);
        }
    }
    if (tid < NC) {
        unsigned v = sc[tid][0] + sc[tid][1] + sc[tid][2] + sc[tid][3];
        atomicAdd(&g_cnt[tid], v);
    }
}

// One CTA of 256 threads: mean, L2-normalize, write output (+ target tail).
__global__ __launch_bounds__(256) void finalize_kernel(float* __restrict__ out, int out_size)
{
    const int tid  = threadIdx.x;
    const int c    = tid >> 6;
    const int lane = tid & 63;
    const int b    = lane * 4;

    const float inv_cnt = 1.0f / (float)g_cnt[c];

    float4 m;
    m.x = g_sum[c * D + b + 0] * inv_cnt;
    m.y = g_sum[c * D + b + 1] * inv_cnt;
    m.z = g_sum[c * D + b + 2] * inv_cnt;
    m.w = g_sum[c * D + b + 3] * inv_cnt;

    float ss = m.x * m.x + m.y * m.y + m.z * m.z + m.w * m.w;

    __shared__ float red[256];
    red[tid] = ss;
    __syncthreads();
    #pragma unroll
    for (int s = 32; s >= 1; s >>= 1) {
        if (lane < s) red[tid] += red[tid + s];
        __syncthreads();
    }

    const float norm = fmaxf(sqrtf(red[c * 64]), 1e-12f);
    const float inv  = 1.0f / norm;

    out[c * D + b + 0] = m.x * inv;
    out[c * D + b + 1] = m.y * inv;
    out[c * D + b + 2] = m.z * inv;
    out[c * D + b + 3] = m.w * inv;

    // target = arange(NC), appended after the [4,256] centers if space exists.
    const int tail = out_size - NC * D;
    if (tail > 0 && tid < tail && tid < NC) {
        out[NC * D + tid] = (float)tid;
    }
}

extern "C" void kernel_launch(void* const* d_in, const int* in_sizes, int n_in,
                              void* d_out, int out_size)
{
    const float4* feat   = (const float4*)d_in[0];
    const int*    labels = (const int*)d_in[1];
    float*        out    = (float*)d_out;

    const int nrows = in_sizes[1];          // 1,000,000

    zero_kernel<<<1, 1024>>>();

    // ~8 CTAs per SM across 152 SMs
    int grid = 1184;
    int maxGrid = (nrows + 3) / 4;
    if (grid > maxGrid) grid = maxGrid;
    accum_kernel<<<grid, 256>>>(feat, labels, nrows);

    finalize_kernel<<<1, 256>>>(out, out_size);
}

// round 5
// speedup vs baseline: 1.1393x; 1.1393x over previous
#include <cuda_runtime.h>
#include <cuda_bf16.h>

#define NC 4
#define D  256

// Scratch: per-class column sums + per-class row counts.
__device__ float        g_sum[NC * D];
__device__ unsigned int g_cnt[NC];

__global__ void zero_kernel() {
    int t = threadIdx.x;
    if (t < NC * D) g_sum[t] = 0.0f;
    if (t < NC)     g_cnt[t] = 0u;
}

// Two packed 1.0f floats / two packed zeros for the f32x2 mask.
#define ONE2 0x3F8000003F800000ULL

// Packed dual-FMA (Blackwell f32x2 pipe): acc.{lo,hi} += v.{lo,hi} * m.{lo,hi}
#define FMA2(acc, v, m) \
    asm("fma.rn.f32x2 %0, %1, %2, %0;" : "+l"(acc) : "l"(v), "l"(m))

// 256 threads/CTA. Each 64-thread group handles 2 rows per iteration.
// lane = float4 (16B) column index within a row; accumulate in f32x2 pairs.
__global__ __launch_bounds__(256) void accum_kernel(
    const ulonglong2* __restrict__ feat,   // [nrows * 64] 16B chunks (2 packed f32 pairs)
    const int*        __restrict__ labels, // [nrows] int32
    int nrows)
{
    const int tid  = threadIdx.x;
    const int grp  = tid >> 6;
    const int lane = tid & 63;

    // 4 classes x 2 f32x2 pairs (covers this thread's 4 floats)
    unsigned long long a00 = 0, a01 = 0, a10 = 0, a11 = 0;
    unsigned long long a20 = 0, a21 = 0, a30 = 0, a31 = 0;
    int c0 = 0, c1 = 0, c2 = 0, c3 = 0;

    const int G = gridDim.x * 4;       // total row-groups
    int row = blockIdx.x * 4 + grp;

    // Main loop: 2 rows per iteration, 4 front-batched independent loads.
    for (; row + G < nrows; row += 2 * G) {
        const int lA = labels[row];
        const int lB = labels[row + G];
        const ulonglong2 vA = feat[(size_t)row       * 64 + lane];
        const ulonglong2 vB = feat[(size_t)(row + G) * 64 + lane];

        {
            const unsigned long long m0 = (lA == 0) ? ONE2 : 0ULL;
            const unsigned long long m1 = (lA == 1) ? ONE2 : 0ULL;
            const unsigned long long m2 = (lA == 2) ? ONE2 : 0ULL;
            const unsigned long long m3 = (lA == 3) ? ONE2 : 0ULL;
            FMA2(a00, vA.x, m0); FMA2(a01, vA.y, m0);
            FMA2(a10, vA.x, m1); FMA2(a11, vA.y, m1);
            FMA2(a20, vA.x, m2); FMA2(a21, vA.y, m2);
            FMA2(a30, vA.x, m3); FMA2(a31, vA.y, m3);
        }
        {
            const unsigned long long m0 = (lB == 0) ? ONE2 : 0ULL;
            const unsigned long long m1 = (lB == 1) ? ONE2 : 0ULL;
            const unsigned long long m2 = (lB == 2) ? ONE2 : 0ULL;
            const unsigned long long m3 = (lB == 3) ? ONE2 : 0ULL;
            FMA2(a00, vB.x, m0); FMA2(a01, vB.y, m0);
            FMA2(a10, vB.x, m1); FMA2(a11, vB.y, m1);
            FMA2(a20, vB.x, m2); FMA2(a21, vB.y, m2);
            FMA2(a30, vB.x, m3); FMA2(a31, vB.y, m3);
        }
        if (lane == 0) {
            c0 += (lA == 0) + (lB == 0);
            c1 += (lA == 1) + (lB == 1);
            c2 += (lA == 2) + (lB == 2);
            c3 += (lA == 3) + (lB == 3);
        }
    }
    // Remainder (at most one row per group)
    for (; row < nrows; row += G) {
        const int lA = labels[row];
        const ulonglong2 vA = feat[(size_t)row * 64 + lane];
        const unsigned long long m0 = (lA == 0) ? ONE2 : 0ULL;
        const unsigned long long m1 = (lA == 1) ? ONE2 : 0ULL;
        const unsigned long long m2 = (lA == 2) ? ONE2 : 0ULL;
        const unsigned long long m3 = (lA == 3) ? ONE2 : 0ULL;
        FMA2(a00, vA.x, m0); FMA2(a01, vA.y, m0);
        FMA2(a10, vA.x, m1); FMA2(a11, vA.y, m1);
        FMA2(a20, vA.x, m2); FMA2(a21, vA.y, m2);
        FMA2(a30, vA.x, m3); FMA2(a31, vA.y, m3);
        if (lane == 0) {
            c0 += (lA == 0); c1 += (lA == 1);
            c2 += (lA == 2); c3 += (lA == 3);
        }
    }

    // Block reduction: s viewed as float[NC][4][256] (16 KB)
    __shared__ unsigned long long s[NC][4][128];
    __shared__ unsigned int sc[NC][4];

    const int p = lane * 2;
    s[0][grp][p] = a00; s[0][grp][p + 1] = a01;
    s[1][grp][p] = a10; s[1][grp][p + 1] = a11;
    s[2][grp][p] = a20; s[2][grp][p + 1] = a21;
    s[3][grp][p] = a30; s[3][grp][p + 1] = a31;

    if (lane == 0) {
        sc[0][grp] = (unsigned)c0; sc[1][grp] = (unsigned)c1;
        sc[2][grp] = (unsigned)c2; sc[3][grp] = (unsigned)c3;
    }
    __syncthreads();

    {
        const float* sf = (const float*)s;
        const int c = tid >> 6;
        const int b = (tid & 63) * 4;
        #pragma unroll
        for (int j = 0; j < 4; j++) {
            float v = sf[(c * 4 + 0) * D + b + j] + sf[(c * 4 + 1) * D + b + j]
                    + sf[(c * 4 + 2) * D + b + j] + sf[(c * 4 + 3) * D + b + j];
            atomicAdd(&g_sum[c * D + b + j], v);
        }
    }
    if (tid < NC) {
        unsigned v = sc[tid][0] + sc[tid][1] + sc[tid][2] + sc[tid][3];
        atomicAdd(&g_cnt[tid], v);
    }
}

// One CTA of 256 threads: mean, L2-normalize, write output (+ target tail).
__global__ __launch_bounds__(256) void finalize_kernel(float* __restrict__ out, int out_size)
{
    const int tid  = threadIdx.x;
    const int c    = tid >> 6;
    const int lane = tid & 63;
    const int b    = lane * 4;

    const float inv_cnt = 1.0f / (float)g_cnt[c];

    float4 m;
    m.x = g_sum[c * D + b + 0] * inv_cnt;
    m.y = g_sum[c * D + b + 1] * inv_cnt;
    m.z = g_sum[c * D + b + 2] * inv_cnt;
    m.w = g_sum[c * D + b + 3] * inv_cnt;

    float ss = m.x * m.x + m.y * m.y + m.z * m.z + m.w * m.w;

    __shared__ float red[256];
    red[tid] = ss;
    __syncthreads();
    #pragma unroll
    for (int s = 32; s >= 1; s >>= 1) {
        if (lane < s) red[tid] += red[tid + s];
        __syncthreads();
    }

    const float norm = fmaxf(sqrtf(red[c * 64]), 1e-12f);
    const float inv  = 1.0f / norm;

    out[c * D + b + 0] = m.x * inv;
    out[c * D + b + 1] = m.y * inv;
    out[c * D + b + 2] = m.z * inv;
    out[c * D + b + 3] = m.w * inv;

    const int tail = out_size - NC * D;
    if (tail > 0 && tid < tail && tid < NC) {
        out[NC * D + tid] = (float)tid;
    }
}

extern "C" void kernel_launch(void* const* d_in, const int* in_sizes, int n_in,
                              void* d_out, int out_size)
{
    const ulonglong2* feat   = (const ulonglong2*)d_in[0];
    const int*        labels = (const int*)d_in[1];
    float*            out    = (float*)d_out;

    const int nrows = in_sizes[1];     // 1,000,000

    // Size the grid to exactly one resident wave (grid-stride + persistent CTAs).
    int numSM = 0, blocksPerSM = 0;
    int grid = 592;  // safe fallback: 4/SM on 148 SMs
    if (cudaDeviceGetAttribute(&numSM, cudaDevAttrMultiProcessorCount, 0) == cudaSuccess &&
        cudaOccupancyMaxActiveBlocksPerMultiprocessor(&blocksPerSM, accum_kernel, 256, 0) == cudaSuccess &&
        numSM > 0 && blocksPerSM > 0) {
        grid = numSM * blocksPerSM;
    }
    int maxGrid = (nrows + 3) / 4;
    if (grid > maxGrid) grid = maxGrid;

    zero_kernel<<<1, 1024>>>();
    accum_kernel<<<grid, 256>>>(feat, labels, nrows);
    finalize_kernel<<<1, 256>>>(out, out_size);
}

// round 6
// speedup vs baseline: 1.2518x; 1.0987x over previous
#include <cuda_runtime.h>
#include <cuda_bf16.h>

#define NC 4
#define D  256

__device__ float        g_sum[NC * D];
__device__ unsigned int g_cnt[NC];
__device__ unsigned int g_done;

__global__ void zero_kernel() {
    int t = threadIdx.x;
    if (t < NC * D) g_sum[t] = 0.0f;
    if (t < NC)     g_cnt[t] = 0u;
    if (t == 0)     g_done = 0u;
}

// Two packed 1.0f floats for the f32x2 mask.
#define ONE2 0x3F8000003F800000ULL
// Packed dual-FMA (Blackwell f32x2): acc += v * m (2 lanes at once)
#define FMA2(acc, v, m) \
    asm("fma.rn.f32x2 %0, %1, %2, %0;" : "+l"(acc) : "l"(v), "l"(m))

// One row-step: apply masked accumulate of one 16B chunk v under label lbl.
#define ACC_ROW(v, lbl)                                                   \
    do {                                                                  \
        const unsigned long long _m0 = ((lbl) == 0) ? ONE2 : 0ULL;        \
        const unsigned long long _m1 = ((lbl) == 1) ? ONE2 : 0ULL;        \
        const unsigned long long _m2 = ((lbl) == 2) ? ONE2 : 0ULL;        \
        const unsigned long long _m3 = ((lbl) == 3) ? ONE2 : 0ULL;        \
        FMA2(a00, (v).x, _m0); FMA2(a01, (v).y, _m0);                     \
        FMA2(a10, (v).x, _m1); FMA2(a11, (v).y, _m1);                     \
        FMA2(a20, (v).x, _m2); FMA2(a21, (v).y, _m2);                     \
        FMA2(a30, (v).x, _m3); FMA2(a31, (v).y, _m3);                     \
    } while (0)

// 256 threads/CTA. CTA processes contiguous chunks of 256 rows.
// Phase A: coalesced label stage into smem (+ free class counting).
// Phase B: each 64-thread group consumes 64 rows; lane = float4 col index.
__global__ __launch_bounds__(256) void accum_kernel(
    const ulonglong2* __restrict__ feat,   // [nrows*64] 16B chunks
    const int*        __restrict__ labels, // [nrows]
    int nrows,
    float* __restrict__ out, int out_size)
{
    const int tid  = threadIdx.x;
    const int grp  = tid >> 6;
    const int lane = tid & 63;

    __shared__ int slab[256];

    unsigned long long a00 = 0, a01 = 0, a10 = 0, a11 = 0;
    unsigned long long a20 = 0, a21 = 0, a30 = 0, a31 = 0;
    int c0 = 0, c1 = 0, c2 = 0, c3 = 0;

    const int nchunks = (nrows + 255) >> 8;

    for (int ch = blockIdx.x; ch < nchunks; ch += gridDim.x) {
        const int rbase = ch << 8;

        // Phase A: stage 256 labels, coalesced; count for free.
        {
            const int idx = rbase + tid;
            const int lbl = (idx < nrows) ? labels[idx] : -1;
            slab[tid] = lbl;
            c0 += (lbl == 0); c1 += (lbl == 1);
            c2 += (lbl == 2); c3 += (lbl == 3);
        }
        __syncthreads();

        // Phase B: this group's 64 rows.
        const int rowbase = rbase + grp * 64;
        const size_t fbase = (size_t)rowbase * 64 + lane;
        const int* myl = &slab[grp * 64];

        if (rowbase + 64 <= nrows) {
            #pragma unroll 4
            for (int j = 0; j < 64; j++) {
                const int lbl = myl[j];
                const ulonglong2 v = feat[fbase + (size_t)j * 64];
                ACC_ROW(v, lbl);
            }
        } else if (rowbase < nrows) {
            const int lim = nrows - rowbase;
            for (int j = 0; j < lim; j++) {
                const int lbl = myl[j];
                const ulonglong2 v = feat[fbase + (size_t)j * 64];
                ACC_ROW(v, lbl);
            }
        }
        __syncthreads();   // before slab is overwritten next chunk
    }

    // ---- Block reduction into global scratch ----
    __shared__ unsigned long long s[NC][4][128];   // float[NC][4][256] view, 16 KB
    __shared__ unsigned int scnt[NC];

    if (tid < NC) scnt[tid] = 0u;

    const int p = lane * 2;
    s[0][grp][p] = a00; s[0][grp][p + 1] = a01;
    s[1][grp][p] = a10; s[1][grp][p + 1] = a11;
    s[2][grp][p] = a20; s[2][grp][p + 1] = a21;
    s[3][grp][p] = a30; s[3][grp][p + 1] = a31;

    // Warp-reduce the per-thread counts, lane0 -> smem
    c0 = __reduce_add_sync(0xffffffffu, c0);
    c1 = __reduce_add_sync(0xffffffffu, c1);
    c2 = __reduce_add_sync(0xffffffffu, c2);
    c3 = __reduce_add_sync(0xffffffffu, c3);
    __syncthreads();
    if ((tid & 31) == 0) {
        atomicAdd(&scnt[0], (unsigned)c0);
        atomicAdd(&scnt[1], (unsigned)c1);
        atomicAdd(&scnt[2], (unsigned)c2);
        atomicAdd(&scnt[3], (unsigned)c3);
    }
    __syncthreads();

    {
        const float* sf = (const float*)s;
        const int c = tid >> 6;
        const int b = (tid & 63) * 4;
        #pragma unroll
        for (int j = 0; j < 4; j++) {
            float v = sf[(c * 4 + 0) * D + b + j] + sf[(c * 4 + 1) * D + b + j]
                    + sf[(c * 4 + 2) * D + b + j] + sf[(c * 4 + 3) * D + b + j];
            atomicAdd(&g_sum[c * D + b + j], v);
        }
    }
    if (tid < NC) atomicAdd(&g_cnt[tid], scnt[tid]);

    // ---- Last block performs the finalize (fused epilogue) ----
    __shared__ unsigned int s_last;
    __threadfence();
    if (tid == 0)
        s_last = (atomicAdd(&g_done, 1u) == (unsigned)(gridDim.x - 1));
    __syncthreads();
    if (!s_last) return;
    __threadfence();   // acquire: see all blocks' atomics

    {
        const int c = tid >> 6;
        const int b = (tid & 63) * 4;

        const float inv_cnt = 1.0f / (float)g_cnt[c];
        float mx = g_sum[c * D + b + 0] * inv_cnt;
        float my = g_sum[c * D + b + 1] * inv_cnt;
        float mz = g_sum[c * D + b + 2] * inv_cnt;
        float mw = g_sum[c * D + b + 3] * inv_cnt;

        __shared__ float red[256];
        red[tid] = mx * mx + my * my + mz * mz + mw * mw;
        __syncthreads();
        #pragma unroll
        for (int st = 32; st >= 1; st >>= 1) {
            if ((tid & 63) < st) red[tid] += red[tid + st];
            __syncthreads();
        }

        const float inv = 1.0f / fmaxf(sqrtf(red[c * 64]), 1e-12f);
        out[c * D + b + 0] = mx * inv;
        out[c * D + b + 1] = my * inv;
        out[c * D + b + 2] = mz * inv;
        out[c * D + b + 3] = mw * inv;

        const int tail = out_size - NC * D;
        if (tail > 0 && tid < tail && tid < NC)
            out[NC * D + tid] = (float)tid;
    }
}

extern "C" void kernel_launch(void* const* d_in, const int* in_sizes, int n_in,
                              void* d_out, int out_size)
{
    const ulonglong2* feat   = (const ulonglong2*)d_in[0];
    const int*        labels = (const int*)d_in[1];
    float*            out    = (float*)d_out;

    const int nrows   = in_sizes[1];        // 1,000,000
    const int nchunks = (nrows + 255) >> 8;

    int numSM = 0, blocksPerSM = 0;
    int grid = 592;
    if (cudaDeviceGetAttribute(&numSM, cudaDevAttrMultiProcessorCount, 0) == cudaSuccess &&
        cudaOccupancyMaxActiveBlocksPerMultiprocessor(&blocksPerSM, accum_kernel, 256, 0) == cudaSuccess &&
        numSM > 0 && blocksPerSM > 0) {
        grid = numSM * blocksPerSM;
    }
    if (grid > nchunks) grid = nchunks;

    zero_kernel<<<1, 1024>>>();
    accum_kernel<<<grid, 256>>>(feat, labels, nrows, out, out_size);
}

// round 7
// speedup vs baseline: 1.3252x; 1.0587x over previous
#include <cuda_runtime.h>
#include <cuda_bf16.h>

#define NC 4
#define D  256

__device__ float        g_sum[NC * D];
__device__ unsigned int g_cnt[NC];
__device__ unsigned int g_done;

__global__ void zero_kernel() {
    int t = threadIdx.x;
    if (t < NC * D) g_sum[t] = 0.0f;
    if (t < NC)     g_cnt[t] = 0u;
    if (t == 0)     g_done = 0u;
}

// Two packed 1.0f floats for the f32x2 mask.
#define ONE2 0x3F8000003F800000ULL
// Packed dual-FMA (Blackwell f32x2): acc += v * m (2 lanes at once)
#define FMA2(acc, v, m) \
    asm("fma.rn.f32x2 %0, %1, %2, %0;" : "+l"(acc) : "l"(v), "l"(m))

#define ACC_ROW(v, lbl)                                                   \
    do {                                                                  \
        const unsigned long long _m0 = ((lbl) == 0) ? ONE2 : 0ULL;        \
        const unsigned long long _m1 = ((lbl) == 1) ? ONE2 : 0ULL;        \
        const unsigned long long _m2 = ((lbl) == 2) ? ONE2 : 0ULL;        \
        const unsigned long long _m3 = ((lbl) == 3) ? ONE2 : 0ULL;        \
        FMA2(a00, (v).x, _m0); FMA2(a01, (v).y, _m0);                     \
        FMA2(a10, (v).x, _m1); FMA2(a11, (v).y, _m1);                     \
        FMA2(a20, (v).x, _m2); FMA2(a21, (v).y, _m2);                     \
        FMA2(a30, (v).x, _m3); FMA2(a31, (v).y, _m3);                     \
    } while (0)

// 256 threads/CTA. Chunk = 128 contiguous rows; each 64-thread group does 32.
// Phase A: coalesced label stage into smem (threads 0-127) + free counting.
// Phase B: group consumes its 32 rows, unroll 8 -> 8 front-batched LDG.128.
__global__ __launch_bounds__(256) void accum_kernel(
    const ulonglong2* __restrict__ feat,   // [nrows*64] 16B chunks
    const int*        __restrict__ labels, // [nrows]
    int nrows,
    float* __restrict__ out, int out_size)
{
    const int tid  = threadIdx.x;
    const int grp  = tid >> 6;
    const int lane = tid & 63;

    __shared__ int slab[128];

    unsigned long long a00 = 0, a01 = 0, a10 = 0, a11 = 0;
    unsigned long long a20 = 0, a21 = 0, a30 = 0, a31 = 0;
    int c0 = 0, c1 = 0, c2 = 0, c3 = 0;

    const int nchunks = (nrows + 127) >> 7;

    for (int ch = blockIdx.x; ch < nchunks; ch += gridDim.x) {
        const int rbase = ch << 7;

        // Phase A: stage 128 labels (coalesced), count for free.
        if (tid < 128) {
            const int idx = rbase + tid;
            const int lbl = (idx < nrows) ? labels[idx] : -1;
            slab[tid] = lbl;
            c0 += (lbl == 0); c1 += (lbl == 1);
            c2 += (lbl == 2); c3 += (lbl == 3);
        }
        __syncthreads();

        // Phase B: this group's 32 rows.
        const int rowbase = rbase + grp * 32;
        const size_t fbase = (size_t)rowbase * 64 + lane;
        const int* myl = &slab[grp * 32];

        int lim = nrows - rowbase;
        if (lim > 32) lim = 32;

        if (lim == 32) {
            #pragma unroll 8
            for (int j = 0; j < 32; j++) {
                const int lbl = myl[j];
                const ulonglong2 v = feat[fbase + (size_t)j * 64];
                ACC_ROW(v, lbl);
            }
        } else {
            for (int j = 0; j < lim; j++) {
                const int lbl = myl[j];
                const ulonglong2 v = feat[fbase + (size_t)j * 64];
                ACC_ROW(v, lbl);
            }
        }
        __syncthreads();   // before slab is overwritten next chunk
    }

    // ---- Block reduction into global scratch ----
    __shared__ unsigned long long s[NC][4][128];   // float[NC][4][256] view, 16 KB
    __shared__ unsigned int scnt[NC];

    if (tid < NC) scnt[tid] = 0u;

    const int p = lane * 2;
    s[0][grp][p] = a00; s[0][grp][p + 1] = a01;
    s[1][grp][p] = a10; s[1][grp][p + 1] = a11;
    s[2][grp][p] = a20; s[2][grp][p + 1] = a21;
    s[3][grp][p] = a30; s[3][grp][p + 1] = a31;

    c0 = __reduce_add_sync(0xffffffffu, c0);
    c1 = __reduce_add_sync(0xffffffffu, c1);
    c2 = __reduce_add_sync(0xffffffffu, c2);
    c3 = __reduce_add_sync(0xffffffffu, c3);
    __syncthreads();
    if ((tid & 31) == 0 && tid < 128) {
        atomicAdd(&scnt[0], (unsigned)c0);
        atomicAdd(&scnt[1], (unsigned)c1);
        atomicAdd(&scnt[2], (unsigned)c2);
        atomicAdd(&scnt[3], (unsigned)c3);
    }
    __syncthreads();

    {
        const float* sf = (const float*)s;
        const int c = tid >> 6;
        const int b = (tid & 63) * 4;
        #pragma unroll
        for (int j = 0; j < 4; j++) {
            float v = sf[(c * 4 + 0) * D + b + j] + sf[(c * 4 + 1) * D + b + j]
                    + sf[(c * 4 + 2) * D + b + j] + sf[(c * 4 + 3) * D + b + j];
            atomicAdd(&g_sum[c * D + b + j], v);
        }
    }
    if (tid < NC) atomicAdd(&g_cnt[tid], scnt[tid]);

    // ---- Last block performs the finalize (fused epilogue) ----
    __shared__ unsigned int s_last;
    __threadfence();
    if (tid == 0)
        s_last = (atomicAdd(&g_done, 1u) == (unsigned)(gridDim.x - 1));
    __syncthreads();
    if (!s_last) return;
    __threadfence();   // acquire: see all blocks' atomics

    {
        const int c = tid >> 6;
        const int b = (tid & 63) * 4;

        const float inv_cnt = 1.0f / (float)g_cnt[c];
        float mx = g_sum[c * D + b + 0] * inv_cnt;
        float my = g_sum[c * D + b + 1] * inv_cnt;
        float mz = g_sum[c * D + b + 2] * inv_cnt;
        float mw = g_sum[c * D + b + 3] * inv_cnt;

        __shared__ float red[256];
        red[tid] = mx * mx + my * my + mz * mz + mw * mw;
        __syncthreads();
        #pragma unroll
        for (int st = 32; st >= 1; st >>= 1) {
            if ((tid & 63) < st) red[tid] += red[tid + st];
            __syncthreads();
        }

        const float inv = 1.0f / fmaxf(sqrtf(red[c * 64]), 1e-12f);
        out[c * D + b + 0] = mx * inv;
        out[c * D + b + 1] = my * inv;
        out[c * D + b + 2] = mz * inv;
        out[c * D + b + 3] = mw * inv;

        const int tail = out_size - NC * D;
        if (tail > 0 && tid < tail && tid < NC)
            out[NC * D + tid] = (float)tid;
    }
}

extern "C" void kernel_launch(void* const* d_in, const int* in_sizes, int n_in,
                              void* d_out, int out_size)
{
    const ulonglong2* feat   = (const ulonglong2*)d_in[0];
    const int*        labels = (const int*)d_in[1];
    float*            out    = (float*)d_out;

    const int nrows   = in_sizes[1];        // 1,000,000
    const int nchunks = (nrows + 127) >> 7;

    int numSM = 0, blocksPerSM = 0;
    int grid = 592;
    if (cudaDeviceGetAttribute(&numSM, cudaDevAttrMultiProcessorCount, 0) == cudaSuccess &&
        cudaOccupancyMaxActiveBlocksPerMultiprocessor(&blocksPerSM, accum_kernel, 256, 0) == cudaSuccess &&
        numSM > 0 && blocksPerSM > 0) {
        grid = numSM * blocksPerSM;
    }
    if (grid > nchunks) grid = nchunks;

    zero_kernel<<<1, 1024>>>();
    accum_kernel<<<grid, 256>>>(feat, labels, nrows, out, out_size);
}